// round 2
// baseline (speedup 1.0000x reference)
#include <cuda_runtime.h>
#include <cstddef>

#define N_NODES  100000
#define N_EDGES  1000000
#define DIM      64
#define N_GRAPHS 2048

// ---------------- scratch (device globals; no allocation allowed) ----------
__device__ float g_t  [N_NODES * DIM];   // h @ W_l  (message term, pre-aggregation)
__device__ float g_r  [N_NODES * DIM];   // h @ W_r + b (self term)
__device__ float g_agg[N_NODES * DIM];   // scatter-add accumulator
__device__ float g_rinv[N_NODES];        // 1/max(deg,1); also used as deg counter
__device__ float g_pool[N_GRAPHS * DIM]; // graph sums
__device__ float g_gcnt[N_GRAPHS];       // graph node counts

// sm_90+ vectorized global reduction (4 floats per op)
__device__ __forceinline__ void red4(float* p, float4 v) {
    asm volatile("red.global.add.v4.f32 [%0], {%1,%2,%3,%4};"
                 :: "l"(p), "f"(v.x), "f"(v.y), "f"(v.z), "f"(v.w) : "memory");
}

__device__ __forceinline__ void fma4(float4& a, float s, const float4& w) {
    a.x += s * w.x; a.y += s * w.y; a.z += s * w.z; a.w += s * w.w;
}
__device__ __forceinline__ float f4get(const float4& v, int k) {
    switch (k) { case 0: return v.x; case 1: return v.y; case 2: return v.z; }
    return v.w;
}

// ---------------- zero kernels --------------------------------------------
__global__ void k_zero_agg() {
    int idx = blockIdx.x * blockDim.x + threadIdx.x;
    if (idx < N_NODES * (DIM / 4))
        reinterpret_cast<float4*>(g_agg)[idx] = make_float4(0.f, 0.f, 0.f, 0.f);
}

__global__ void k_zero_stats() {
    int i = blockIdx.x * blockDim.x + threadIdx.x;
    if (i < N_NODES)        g_rinv[i] = 0.f;
    if (i < N_GRAPHS * DIM) g_pool[i] = 0.f;
    if (i < N_GRAPHS)       g_gcnt[i] = 0.f;
}

// ---------------- degree + graph counts (one pass) -------------------------
__global__ void k_deg_gcnt(const int* __restrict__ dst, const int* __restrict__ batch) {
    int i = blockIdx.x * blockDim.x + threadIdx.x;
    if (i < N_EDGES) atomicAdd(&g_rinv[dst[i]], 1.0f);
    if (i < N_NODES) atomicAdd(&g_gcnt[batch[i]], 1.0f);
}

__global__ void k_rinv() {
    int i = blockIdx.x * blockDim.x + threadIdx.x;
    if (i < N_NODES) g_rinv[i] = 1.0f / fmaxf(g_rinv[i], 1.0f);
}

// ---------------- fused dual GEMM:  t = h@Wl ;  r = h@Wr + b ---------------
// Register-blocked: block = 256 threads handles a 128-node tile.
// Thread (cg = tid&7, ng = tid>>3) computes 4 nodes (ng + 32*i) x 16 cols
// (float4 columns cg + 8*j; j=0,1 -> Wl/t, j=2,3 -> Wr/r).
// h tile (128 x 64 fp32, stride 17 f4) + W tile (64 x 128) live in dyn smem.
// LAYER==1: h = emb[x[node]];  LAYER==2: h = relu(agg*rinv + r)  (fused epilogue).
template<int LAYER>
__global__ __launch_bounds__(256, 2) void k_transform(
    const float* __restrict__ emb, const int* __restrict__ xidx,
    const float* __restrict__ Wl, const float* __restrict__ Wr,
    const float* __restrict__ b)
{
    extern __shared__ float4 smem[];
    float4* h_s = smem;                 // 128 * 17 float4
    float4* w_s = smem + 128 * 17;      // 64 * 32 float4 (Wl cols 0-15, Wr 16-31)

    const int tid  = threadIdx.x;
    const int base = blockIdx.x * 128;

    // Stage W (both matrices, interleaved per-k row)
    for (int idx = tid; idx < 64 * 16; idx += 256) {
        int k = idx >> 4, c4 = idx & 15;
        w_s[k * 32 + c4]      = __ldg(reinterpret_cast<const float4*>(Wl) + idx);
        w_s[k * 32 + 16 + c4] = __ldg(reinterpret_cast<const float4*>(Wr) + idx);
    }
    // Stage h tile (with fused producer)
    for (int idx = tid; idx < 128 * 16; idx += 256) {
        int row = idx >> 4, c4 = idx & 15;
        int node = base + row;
        float4 v = make_float4(0.f, 0.f, 0.f, 0.f);
        if (node < N_NODES) {
            if (LAYER == 1) {
                int e = __ldg(xidx + node);
                v = __ldg(reinterpret_cast<const float4*>(emb) + (size_t)e * 16 + c4);
            } else {
                float  s = g_rinv[node];
                float4 a = reinterpret_cast<const float4*>(g_agg)[(size_t)node * 16 + c4];
                float4 r = reinterpret_cast<const float4*>(g_r  )[(size_t)node * 16 + c4];
                v.x = fmaxf(a.x * s + r.x, 0.f);
                v.y = fmaxf(a.y * s + r.y, 0.f);
                v.z = fmaxf(a.z * s + r.z, 0.f);
                v.w = fmaxf(a.w * s + r.w, 0.f);
            }
        }
        h_s[row * 17 + c4] = v;
    }
    __syncthreads();

    const int cg = tid & 7;     // column group: f4 cols cg + 8*j
    const int ng = tid >> 3;    // node group:   nodes ng + 32*i

    float4 bb0 = __ldg(reinterpret_cast<const float4*>(b) + cg);
    float4 bb1 = __ldg(reinterpret_cast<const float4*>(b) + cg + 8);

    float4 acc[4][4];
    #pragma unroll
    for (int i = 0; i < 4; i++)
        #pragma unroll
        for (int j = 0; j < 4; j++)
            acc[i][j] = make_float4(0.f, 0.f, 0.f, 0.f);

    #pragma unroll 4
    for (int k4 = 0; k4 < 16; k4++) {
        float4 hv[4];
        #pragma unroll
        for (int i = 0; i < 4; i++)
            hv[i] = h_s[(ng + 32 * i) * 17 + k4];
        #pragma unroll
        for (int kk = 0; kk < 4; kk++) {
            #pragma unroll
            for (int j = 0; j < 4; j++) {
                float4 w = w_s[(k4 * 4 + kk) * 32 + cg + 8 * j];
                #pragma unroll
                for (int i = 0; i < 4; i++)
                    fma4(acc[i][j], f4get(hv[i], kk), w);
            }
        }
    }

    #pragma unroll
    for (int i = 0; i < 4; i++) {
        int node = base + ng + 32 * i;
        if (node >= N_NODES) continue;
        float4* tp = reinterpret_cast<float4*>(g_t) + (size_t)node * 16;
        float4* rp = reinterpret_cast<float4*>(g_r) + (size_t)node * 16;
        tp[cg]     = acc[i][0];
        tp[cg + 8] = acc[i][1];
        float4 r0 = acc[i][2];
        r0.x += bb0.x; r0.y += bb0.y; r0.z += bb0.z; r0.w += bb0.w;
        rp[cg]     = r0;
        float4 r1 = acc[i][3];
        r1.x += bb1.x; r1.y += bb1.y; r1.z += bb1.z; r1.w += bb1.w;
        rp[cg + 8] = r1;
    }
}

// ---------------- edge scatter:  agg[dst] += t[src] ------------------------
__global__ void k_edge(const int* __restrict__ src, const int* __restrict__ dst) {
    int idx = blockIdx.x * blockDim.x + threadIdx.x;
    if (idx >= N_EDGES * 4) return;
    int e = idx >> 2, q = idx & 3;
    int s = __ldg(src + e);
    int d = __ldg(dst + e);
    const float4* tp = reinterpret_cast<const float4*>(g_t + (size_t)s * DIM) + q * 4;
    float*        ap = g_agg + (size_t)d * DIM + q * 16;
    float4 v0 = __ldg(tp + 0), v1 = __ldg(tp + 1);
    float4 v2 = __ldg(tp + 2), v3 = __ldg(tp + 3);
    red4(ap +  0, v0); red4(ap +  4, v1);
    red4(ap +  8, v2); red4(ap + 12, v3);
}

// ---------------- pool with fused node epilogue ----------------------------
__global__ void k_pool(const int* __restrict__ batch) {
    int idx = blockIdx.x * blockDim.x + threadIdx.x;
    if (idx >= N_NODES * (DIM / 4)) return;
    int i = idx >> 4;
    float  s = g_rinv[i];
    float4 a = reinterpret_cast<const float4*>(g_agg)[idx];
    float4 r = reinterpret_cast<const float4*>(g_r)[idx];
    float4 h;
    h.x = fmaxf(a.x * s + r.x, 0.f);
    h.y = fmaxf(a.y * s + r.y, 0.f);
    h.z = fmaxf(a.z * s + r.z, 0.f);
    h.w = fmaxf(a.w * s + r.w, 0.f);
    int g = __ldg(batch + i);
    red4(&g_pool[(size_t)g * DIM + (idx & 15) * 4], h);
}

// ---------------- classifier:  out = (pool/gcnt) @ Wout + bout -------------
__global__ void k_out(const float* __restrict__ Wout, const float* __restrict__ bout,
                      float* __restrict__ out) {
    int gid  = (blockIdx.x * blockDim.x + threadIdx.x) >> 5;
    int lane = threadIdx.x & 31;
    if (gid >= N_GRAPHS) return;
    float inv = 1.0f / fmaxf(g_gcnt[gid], 1.0f);
    float p0 = 0.f, p1 = 0.f;
    #pragma unroll
    for (int t = 0; t < 2; t++) {
        int j = lane * 2 + t;
        float v = g_pool[(size_t)gid * DIM + j] * inv;
        p0 += v * __ldg(Wout + j * 2 + 0);
        p1 += v * __ldg(Wout + j * 2 + 1);
    }
    #pragma unroll
    for (int off = 16; off; off >>= 1) {
        p0 += __shfl_down_sync(0xFFFFFFFFu, p0, off);
        p1 += __shfl_down_sync(0xFFFFFFFFu, p1, off);
    }
    if (lane == 0) {
        out[gid * 2 + 0] = p0 + __ldg(bout + 0);
        out[gid * 2 + 1] = p1 + __ldg(bout + 1);
    }
}

// ---------------- launch ---------------------------------------------------
extern "C" void kernel_launch(void* const* d_in, const int* in_sizes, int n_in,
                              void* d_out, int out_size) {
    const int*   x     = (const int*)  d_in[0];
    const int*   ei    = (const int*)  d_in[1];   // [2, E] row-major
    const int*   batch = (const int*)  d_in[2];
    const float* emb   = (const float*)d_in[3];
    const float* W1l   = (const float*)d_in[4];
    const float* b1    = (const float*)d_in[5];
    const float* W1r   = (const float*)d_in[6];
    const float* W2l   = (const float*)d_in[7];
    const float* b2    = (const float*)d_in[8];
    const float* W2r   = (const float*)d_in[9];
    const float* Wout  = (const float*)d_in[10];
    const float* bout  = (const float*)d_in[11];
    float* out = (float*)d_out;

    const int* src = ei;
    const int* dst = ei + N_EDGES;

    const int ZSTATS = (N_GRAPHS * DIM > N_NODES) ? N_GRAPHS * DIM : N_NODES;
    const int NV4    = N_NODES * (DIM / 4);
    const int TBLK   = (N_NODES + 127) / 128;          // 782 transform blocks
    const int TSMEM  = (128 * 17 + 64 * 32) * 16;      // 67584 B dynamic smem

    // executes at capture time; attribute persists across graph replays
    cudaFuncSetAttribute(k_transform<1>, cudaFuncAttributeMaxDynamicSharedMemorySize, TSMEM);
    cudaFuncSetAttribute(k_transform<2>, cudaFuncAttributeMaxDynamicSharedMemorySize, TSMEM);

    k_zero_stats<<<(ZSTATS + 255) / 256, 256>>>();
    k_deg_gcnt  <<<(N_EDGES + 255) / 256, 256>>>(dst, batch);
    k_rinv      <<<(N_NODES + 255) / 256, 256>>>();

    // layer 1
    k_transform<1><<<TBLK, 256, TSMEM>>>(emb, x, W1l, W1r, b1);
    k_zero_agg    <<<(NV4 + 255) / 256, 256>>>();
    k_edge        <<<(N_EDGES * 4 + 255) / 256, 256>>>(src, dst);

    // layer 2 (node epilogue of layer 1 fused into transform load phase)
    k_transform<2><<<TBLK, 256, TSMEM>>>(nullptr, nullptr, W2l, W2r, b2);
    k_zero_agg    <<<(NV4 + 255) / 256, 256>>>();
    k_edge        <<<(N_EDGES * 4 + 255) / 256, 256>>>(src, dst);

    // pool (node epilogue of layer 2 fused) + classifier
    k_pool<<<(NV4 + 255) / 256, 256>>>(batch);
    k_out <<<(N_GRAPHS * 32 + 255) / 256, 256>>>(Wout, bout, out);
}

// round 6
// speedup vs baseline: 1.2866x; 1.2866x over previous
#include <cuda_runtime.h>
#include <cstddef>

#define N_NODES  100000
#define N_EDGES  1000000
#define DIM      64
#define N_GRAPHS 2048

// ---------------- scratch (device globals; no allocation allowed) ----------
__device__ float g_t  [N_NODES * DIM];   // h @ W_l  (message term)
__device__ float g_r  [N_NODES * DIM];   // h @ W_r + b (self term)
__device__ float g_agg[N_NODES * DIM];   // scatter-add accumulator
__device__ float g_deg[N_NODES];         // edge in-degree (float)
__device__ float g_pool[N_GRAPHS * DIM]; // graph sums
__device__ float g_gcnt[N_GRAPHS];       // graph node counts

// sm_90+ vectorized global reduction (4 floats per op)
__device__ __forceinline__ void red4(float* p, float4 v) {
    asm volatile("red.global.add.v4.f32 [%0], {%1,%2,%3,%4};"
                 :: "l"(p), "f"(v.x), "f"(v.y), "f"(v.z), "f"(v.w) : "memory");
}

// ---------------- init: zero deg/pool/gcnt --------------------------------
__global__ void k_zero_stats() {
    int i = blockIdx.x * blockDim.x + threadIdx.x;
    if (i < N_NODES)        g_deg[i]  = 0.f;
    if (i < N_GRAPHS * DIM) g_pool[i] = 0.f;
    if (i < N_GRAPHS)       g_gcnt[i] = 0.f;
}

// ---------------- degree + graph counts (one pass) -------------------------
__global__ void k_deg_gcnt(const int* __restrict__ dst, const int* __restrict__ batch) {
    int i = blockIdx.x * blockDim.x + threadIdx.x;
    if (i < N_EDGES) atomicAdd(&g_deg[dst[i]], 1.0f);
    if (i < N_NODES) atomicAdd(&g_gcnt[batch[i]], 1.0f);
}

// ---------------- fused dual matmul:  t = h@Wl ;  r = h@Wr + b -------------
// One thread per node (round-1 proven design). h-row in 64 regs; Wl|Wr packed
// in a 64x128 smem tile read as warp-broadcast float4s.
// LAYER==1: h = emb[x[i]].  LAYER==2: h = relu(agg/max(deg,1) + r) (fused).
// Each thread also zeroes its node's g_agg row for the next edge pass
// (transform<2> reads its own row first -> intra-thread ordering, no hazard).
template<int LAYER>
__global__ __launch_bounds__(128) void k_transform(
    const float* __restrict__ emb, const int* __restrict__ xidx,
    const float* __restrict__ Wl, const float* __restrict__ Wr,
    const float* __restrict__ b)
{
    __shared__ float Ws[DIM * 128];   // [k][j]; j<64 -> Wl, j>=64 -> Wr
    __shared__ float bs[DIM];
    int tid = threadIdx.x;
    for (int idx = tid; idx < DIM * DIM; idx += 128) {
        int row = idx >> 6, col = idx & 63;
        Ws[row * 128 + col]      = Wl[idx];
        Ws[row * 128 + 64 + col] = Wr[idx];
    }
    if (tid < DIM) bs[tid] = b[tid];
    __syncthreads();

    int i = blockIdx.x * 128 + tid;
    if (i >= N_NODES) return;

    float hv[DIM];
    float4* aggp = reinterpret_cast<float4*>(g_agg) + (size_t)i * 16;
    if (LAYER == 1) {
        const float* hrow = emb + (size_t)__ldg(xidx + i) * DIM;
        #pragma unroll
        for (int k = 0; k < DIM / 4; k++) {
            float4 v = __ldg(reinterpret_cast<const float4*>(hrow) + k);
            hv[4 * k + 0] = v.x; hv[4 * k + 1] = v.y;
            hv[4 * k + 2] = v.z; hv[4 * k + 3] = v.w;
        }
    } else {
        float s = 1.0f / fmaxf(g_deg[i], 1.0f);
        const float4* rp = reinterpret_cast<const float4*>(g_r) + (size_t)i * 16;
        #pragma unroll
        for (int k = 0; k < DIM / 4; k++) {
            float4 a = aggp[k];
            float4 r = __ldg(rp + k);
            hv[4 * k + 0] = fmaxf(a.x * s + r.x, 0.f);
            hv[4 * k + 1] = fmaxf(a.y * s + r.y, 0.f);
            hv[4 * k + 2] = fmaxf(a.z * s + r.z, 0.f);
            hv[4 * k + 3] = fmaxf(a.w * s + r.w, 0.f);
        }
    }

    // zero own agg row for the upcoming edge pass (own row already consumed)
    #pragma unroll
    for (int k = 0; k < DIM / 4; k++)
        aggp[k] = make_float4(0.f, 0.f, 0.f, 0.f);

    const float4* Ws4 = reinterpret_cast<const float4*>(Ws);
    float4* tout = reinterpret_cast<float4*>(g_t + (size_t)i * DIM);
    float4* rout = reinterpret_cast<float4*>(g_r + (size_t)i * DIM);

    for (int jt = 0; jt < 32; jt++) {                 // rolled: keeps I$ small
        float4 acc = make_float4(0.f, 0.f, 0.f, 0.f);
        #pragma unroll
        for (int k = 0; k < DIM; k++) {               // unrolled: hv in regs
            float4 w = Ws4[k * 32 + jt];              // warp-broadcast LDS.128
            float hk = hv[k];
            acc.x += hk * w.x; acc.y += hk * w.y;
            acc.z += hk * w.z; acc.w += hk * w.w;
        }
        if (jt < 16) {
            tout[jt] = acc;
        } else {
            int j4 = jt - 16;
            acc.x += bs[4 * j4 + 0]; acc.y += bs[4 * j4 + 1];
            acc.z += bs[4 * j4 + 2]; acc.w += bs[4 * j4 + 3];
            rout[j4] = acc;
        }
    }
}

// ---------------- edge scatter:  agg[dst] += t[src] ------------------------
// 4 threads per edge; each moves 16 floats via 4x (LDG.128 + red.v4).
__global__ void k_edge(const int* __restrict__ src, const int* __restrict__ dst) {
    int idx = blockIdx.x * blockDim.x + threadIdx.x;
    if (idx >= N_EDGES * 4) return;
    int e = idx >> 2, q = idx & 3;
    int s = __ldg(src + e);
    int d = __ldg(dst + e);
    const float4* tp = reinterpret_cast<const float4*>(g_t + (size_t)s * DIM) + q * 4;
    float*        ap = g_agg + (size_t)d * DIM + q * 16;
    float4 v0 = __ldg(tp + 0), v1 = __ldg(tp + 1);
    float4 v2 = __ldg(tp + 2), v3 = __ldg(tp + 3);
    red4(ap +  0, v0); red4(ap +  4, v1);
    red4(ap +  8, v2); red4(ap + 12, v3);
}

// ---------------- pool: fused node epilogue + sorted-run aggregation -------
// Thread (c4 = tid&15) walks 8 consecutive nodes for its column chunk,
// accumulating locally while the (sorted) graph id stays constant and
// flushing one red4 per run segment -> ~6-8x fewer pool atomics.
__global__ void k_pool(const int* __restrict__ batch) {
    int gid = blockIdx.x * blockDim.x + threadIdx.x;
    int c4 = gid & 15;
    int n0 = (gid >> 4) * 8;
    if (n0 >= N_NODES) return;

    float4 accum = make_float4(0.f, 0.f, 0.f, 0.f);
    int cur_g = __ldg(batch + n0);
    #pragma unroll
    for (int j = 0; j < 8; j++) {
        int node = n0 + j;                       // N_NODES % 8 == 0: no guard
        int g = __ldg(batch + node);
        if (g != cur_g) {
            red4(&g_pool[(size_t)cur_g * DIM + c4 * 4], accum);
            accum = make_float4(0.f, 0.f, 0.f, 0.f);
            cur_g = g;
        }
        float  s = 1.0f / fmaxf(g_deg[node], 1.0f);
        float4 a = reinterpret_cast<const float4*>(g_agg)[(size_t)node * 16 + c4];
        float4 r = reinterpret_cast<const float4*>(g_r  )[(size_t)node * 16 + c4];
        accum.x += fmaxf(a.x * s + r.x, 0.f);
        accum.y += fmaxf(a.y * s + r.y, 0.f);
        accum.z += fmaxf(a.z * s + r.z, 0.f);
        accum.w += fmaxf(a.w * s + r.w, 0.f);
    }
    red4(&g_pool[(size_t)cur_g * DIM + c4 * 4], accum);
}

// ---------------- classifier:  out = (pool/gcnt) @ Wout + bout -------------
__global__ void k_out(const float* __restrict__ Wout, const float* __restrict__ bout,
                      float* __restrict__ out) {
    int gid  = (blockIdx.x * blockDim.x + threadIdx.x) >> 5;
    int lane = threadIdx.x & 31;
    if (gid >= N_GRAPHS) return;
    float inv = 1.0f / fmaxf(g_gcnt[gid], 1.0f);
    float p0 = 0.f, p1 = 0.f;
    #pragma unroll
    for (int t = 0; t < 2; t++) {
        int j = lane * 2 + t;
        float v = g_pool[(size_t)gid * DIM + j] * inv;
        p0 += v * __ldg(Wout + j * 2 + 0);
        p1 += v * __ldg(Wout + j * 2 + 1);
    }
    #pragma unroll
    for (int off = 16; off; off >>= 1) {
        p0 += __shfl_down_sync(0xFFFFFFFFu, p0, off);
        p1 += __shfl_down_sync(0xFFFFFFFFu, p1, off);
    }
    if (lane == 0) {
        out[gid * 2 + 0] = p0 + __ldg(bout + 0);
        out[gid * 2 + 1] = p1 + __ldg(bout + 1);
    }
}

// ---------------- launch ---------------------------------------------------
extern "C" void kernel_launch(void* const* d_in, const int* in_sizes, int n_in,
                              void* d_out, int out_size) {
    const int*   x     = (const int*)  d_in[0];
    const int*   ei    = (const int*)  d_in[1];   // [2, E] row-major
    const int*   batch = (const int*)  d_in[2];
    const float* emb   = (const float*)d_in[3];
    const float* W1l   = (const float*)d_in[4];
    const float* b1    = (const float*)d_in[5];
    const float* W1r   = (const float*)d_in[6];
    const float* W2l   = (const float*)d_in[7];
    const float* b2    = (const float*)d_in[8];
    const float* W2r   = (const float*)d_in[9];
    const float* Wout  = (const float*)d_in[10];
    const float* bout  = (const float*)d_in[11];
    float* out = (float*)d_out;

    const int* src = ei;
    const int* dst = ei + N_EDGES;

    const int ZSTATS = (N_GRAPHS * DIM > N_NODES) ? N_GRAPHS * DIM : N_NODES;
    const int TBLK   = (N_NODES + 127) / 128;
    const int PTHREADS = (N_NODES / 8) * 16;      // 200000

    k_zero_stats<<<(ZSTATS + 255) / 256, 256>>>();
    k_deg_gcnt  <<<(N_EDGES + 255) / 256, 256>>>(dst, batch);

    // layer 1 (transform zeroes agg rows itself)
    k_transform<1><<<TBLK, 128>>>(emb, x, W1l, W1r, b1);
    k_edge        <<<(N_EDGES * 4 + 255) / 256, 256>>>(src, dst);

    // layer 2 (layer-1 node epilogue fused into staging; agg re-zeroed inline)
    k_transform<2><<<TBLK, 128>>>(nullptr, nullptr, W2l, W2r, b2);
    k_edge        <<<(N_EDGES * 4 + 255) / 256, 256>>>(src, dst);

    // pool (layer-2 node epilogue fused) + classifier
    k_pool<<<(PTHREADS + 255) / 256, 256>>>(batch);
    k_out <<<(N_GRAPHS * 32 + 255) / 256, 256>>>(Wout, bout, out);
}

// round 10
// speedup vs baseline: 1.7178x; 1.3352x over previous
#include <cuda_runtime.h>
#include <cstddef>

#define N_NODES  100000
#define N_EDGES  1000000
#define DIM      64
#define N_GRAPHS 2048
#define SCAN_BS  1024
#define N_CHUNKS ((N_NODES + SCAN_BS - 1) / SCAN_BS)   // 98

// ---------------- scratch (device globals; no allocation allowed) ----------
__device__ float g_t   [N_NODES * DIM];   // h @ W_l  (message term)
__device__ float g_r   [N_NODES * DIM];   // h @ W_r + b (self term)
__device__ float g_agg [N_NODES * DIM];   // per-node mean of neighbor messages
__device__ float g_pool[N_GRAPHS * DIM];  // graph sums
__device__ float g_gcnt[N_GRAPHS];        // graph node counts
__device__ int   g_cnt [N_NODES];         // in-degree (CSR row lengths)
__device__ int   g_beg [N_NODES];         // CSR row starts (exclusive scan)
__device__ int   g_cur [N_NODES];         // fill cursors
__device__ int   g_esrc[N_EDGES];         // CSR: src node per slot
__device__ int   g_csum[128];             // per-chunk sums
__device__ int   g_coff[128];             // per-chunk exclusive offsets

// sm_90+ vectorized global reduction (4 floats per op)
__device__ __forceinline__ void red4(float* p, float4 v) {
    asm volatile("red.global.add.v4.f32 [%0], {%1,%2,%3,%4};"
                 :: "l"(p), "f"(v.x), "f"(v.y), "f"(v.z), "f"(v.w) : "memory");
}

// ---------------- init ------------------------------------------------------
__global__ void k_zero_stats() {
    int i = blockIdx.x * blockDim.x + threadIdx.x;
    if (i < N_NODES)        g_cnt[i]  = 0;
    if (i < N_GRAPHS * DIM) g_pool[i] = 0.f;
    if (i < N_GRAPHS)       g_gcnt[i] = 0.f;
}

// ---------------- histogram: in-degree + graph counts ----------------------
__global__ void k_hist(const int* __restrict__ dst, const int* __restrict__ batch) {
    int i = blockIdx.x * blockDim.x + threadIdx.x;
    if (i < N_EDGES) atomicAdd(&g_cnt[dst[i]], 1);
    if (i < N_NODES) atomicAdd(&g_gcnt[batch[i]], 1.0f);
}

// ---------------- 3-kernel exclusive scan of g_cnt -> g_beg ----------------
__global__ __launch_bounds__(SCAN_BS) void k_scan1() {
    __shared__ int sh[SCAN_BS];
    int t = threadIdx.x;
    int i = blockIdx.x * SCAN_BS + t;
    sh[t] = (i < N_NODES) ? g_cnt[i] : 0;
    #pragma unroll
    for (int off = SCAN_BS / 2; off; off >>= 1) {
        __syncthreads();
        if (t < off) sh[t] += sh[t + off];
    }
    if (t == 0) g_csum[blockIdx.x] = sh[0];
}

__global__ void k_scan2() {              // 1 block, 128 threads
    __shared__ int sh[128];
    int t = threadIdx.x;
    sh[t] = (t < N_CHUNKS) ? g_csum[t] : 0;
    __syncthreads();
    #pragma unroll
    for (int off = 1; off < 128; off <<= 1) {   // inclusive Hillis-Steele
        int u = (t >= off) ? sh[t - off] : 0;
        __syncthreads();
        sh[t] += u;
        __syncthreads();
    }
    if (t < N_CHUNKS) g_coff[t] = (t ? sh[t - 1] : 0);   // exclusive
}

__global__ __launch_bounds__(SCAN_BS) void k_scan3() {
    __shared__ int sh[SCAN_BS];
    int t = threadIdx.x;
    int i = blockIdx.x * SCAN_BS + t;
    int v = (i < N_NODES) ? g_cnt[i] : 0;
    sh[t] = v;
    __syncthreads();
    #pragma unroll
    for (int off = 1; off < SCAN_BS; off <<= 1) {        // inclusive scan
        int u = (t >= off) ? sh[t - off] : 0;
        __syncthreads();
        sh[t] += u;
        __syncthreads();
    }
    if (i < N_NODES) {
        int excl = g_coff[blockIdx.x] + sh[t] - v;
        g_beg[i] = excl;
        g_cur[i] = excl;
    }
}

// ---------------- CSR fill ---------------------------------------------------
__global__ void k_fill(const int* __restrict__ src, const int* __restrict__ dst) {
    int e = blockIdx.x * blockDim.x + threadIdx.x;
    if (e >= N_EDGES) return;
    int slot = atomicAdd(&g_cur[dst[e]], 1);
    g_esrc[slot] = src[e];
}

// ---------------- fused dual matmul:  t = h@Wl ;  r = h@Wr + b -------------
// One thread per node. h-row in 64 regs; Wl|Wr packed in a 64x128 smem tile
// read as warp-broadcast float4s.
// LAYER==1: h = emb[x[i]].  LAYER==2: h = relu(agg + r) (agg already mean).
template<int LAYER>
__global__ __launch_bounds__(128) void k_transform(
    const float* __restrict__ emb, const int* __restrict__ xidx,
    const float* __restrict__ Wl, const float* __restrict__ Wr,
    const float* __restrict__ b)
{
    __shared__ float Ws[DIM * 128];   // [k][j]; j<64 -> Wl, j>=64 -> Wr
    __shared__ float bs[DIM];
    int tid = threadIdx.x;
    for (int idx = tid; idx < DIM * DIM; idx += 128) {
        int row = idx >> 6, col = idx & 63;
        Ws[row * 128 + col]      = Wl[idx];
        Ws[row * 128 + 64 + col] = Wr[idx];
    }
    if (tid < DIM) bs[tid] = b[tid];
    __syncthreads();

    int i = blockIdx.x * 128 + tid;
    if (i >= N_NODES) return;

    float hv[DIM];
    if (LAYER == 1) {
        const float* hrow = emb + (size_t)__ldg(xidx + i) * DIM;
        #pragma unroll
        for (int k = 0; k < DIM / 4; k++) {
            float4 v = __ldg(reinterpret_cast<const float4*>(hrow) + k);
            hv[4 * k + 0] = v.x; hv[4 * k + 1] = v.y;
            hv[4 * k + 2] = v.z; hv[4 * k + 3] = v.w;
        }
    } else {
        const float4* ap = reinterpret_cast<const float4*>(g_agg) + (size_t)i * 16;
        const float4* rp = reinterpret_cast<const float4*>(g_r)   + (size_t)i * 16;
        #pragma unroll
        for (int k = 0; k < DIM / 4; k++) {
            float4 a = __ldg(ap + k);
            float4 r = __ldg(rp + k);
            hv[4 * k + 0] = fmaxf(a.x + r.x, 0.f);
            hv[4 * k + 1] = fmaxf(a.y + r.y, 0.f);
            hv[4 * k + 2] = fmaxf(a.z + r.z, 0.f);
            hv[4 * k + 3] = fmaxf(a.w + r.w, 0.f);
        }
    }

    const float4* Ws4 = reinterpret_cast<const float4*>(Ws);
    float4* tout = reinterpret_cast<float4*>(g_t + (size_t)i * DIM);
    float4* rout = reinterpret_cast<float4*>(g_r + (size_t)i * DIM);

    for (int jt = 0; jt < 32; jt++) {                 // rolled: keeps I$ small
        float4 acc = make_float4(0.f, 0.f, 0.f, 0.f);
        #pragma unroll
        for (int k = 0; k < DIM; k++) {               // unrolled: hv in regs
            float4 w = Ws4[k * 32 + jt];              // warp-broadcast LDS.128
            float hk = hv[k];
            acc.x += hk * w.x; acc.y += hk * w.y;
            acc.z += hk * w.z; acc.w += hk * w.w;
        }
        if (jt < 16) {
            tout[jt] = acc;
        } else {
            int j4 = jt - 16;
            acc.x += bs[4 * j4 + 0]; acc.y += bs[4 * j4 + 1];
            acc.z += bs[4 * j4 + 2]; acc.w += bs[4 * j4 + 3];
            rout[j4] = acc;
        }
    }
}

// ---------------- CSR gather-aggregate:  agg[i] = mean_{s in N(i)} t[s] ----
// One warp per destination node. Each edge iteration loads a full 256B source
// row coalesced (32 lanes x float2); atomic-free; writes mean, coalesced.
__global__ __launch_bounds__(256) void k_agg() {
    int w    = (blockIdx.x * blockDim.x + threadIdx.x) >> 5;
    int lane = threadIdx.x & 31;
    if (w >= N_NODES) return;
    int beg = __ldg(&g_beg[w]);          // warp-broadcast
    int cnt = __ldg(&g_cnt[w]);

    const float2* tb = reinterpret_cast<const float2*>(g_t);
    float2 a0 = make_float2(0.f, 0.f), a1 = make_float2(0.f, 0.f);

    for (int j0 = 0; j0 < cnt; j0 += 32) {
        int jj = j0 + lane;
        int s_pre = (jj < cnt) ? __ldg(g_esrc + beg + jj) : 0;
        int m = min(cnt - j0, 32);
        int u = 0;
        for (; u + 1 < m; u += 2) {
            int s0 = __shfl_sync(0xFFFFFFFFu, s_pre, u);
            int s1 = __shfl_sync(0xFFFFFFFFu, s_pre, u + 1);
            float2 v0 = __ldg(tb + (size_t)s0 * 32 + lane);
            float2 v1 = __ldg(tb + (size_t)s1 * 32 + lane);
            a0.x += v0.x; a0.y += v0.y;
            a1.x += v1.x; a1.y += v1.y;
        }
        if (u < m) {
            int s0 = __shfl_sync(0xFFFFFFFFu, s_pre, u);
            float2 v0 = __ldg(tb + (size_t)s0 * 32 + lane);
            a0.x += v0.x; a0.y += v0.y;
        }
    }
    float sc = 1.0f / fmaxf((float)cnt, 1.0f);
    float2 out;
    out.x = (a0.x + a1.x) * sc;
    out.y = (a0.y + a1.y) * sc;
    reinterpret_cast<float2*>(g_agg)[(size_t)w * 32 + lane] = out;
}

// ---------------- pool: fused node epilogue + sorted-run aggregation -------
__global__ void k_pool(const int* __restrict__ batch) {
    int gid = blockIdx.x * blockDim.x + threadIdx.x;
    int c4 = gid & 15;
    int n0 = (gid >> 4) * 8;
    if (n0 >= N_NODES) return;

    float4 accum = make_float4(0.f, 0.f, 0.f, 0.f);
    int cur_g = __ldg(batch + n0);
    #pragma unroll
    for (int j = 0; j < 8; j++) {
        int node = n0 + j;                       // N_NODES % 8 == 0: no guard
        int g = __ldg(batch + node);
        if (g != cur_g) {
            red4(&g_pool[(size_t)cur_g * DIM + c4 * 4], accum);
            accum = make_float4(0.f, 0.f, 0.f, 0.f);
            cur_g = g;
        }
        float4 a = reinterpret_cast<const float4*>(g_agg)[(size_t)node * 16 + c4];
        float4 r = reinterpret_cast<const float4*>(g_r  )[(size_t)node * 16 + c4];
        accum.x += fmaxf(a.x + r.x, 0.f);
        accum.y += fmaxf(a.y + r.y, 0.f);
        accum.z += fmaxf(a.z + r.z, 0.f);
        accum.w += fmaxf(a.w + r.w, 0.f);
    }
    red4(&g_pool[(size_t)cur_g * DIM + c4 * 4], accum);
}

// ---------------- classifier:  out = (pool/gcnt) @ Wout + bout -------------
__global__ void k_out(const float* __restrict__ Wout, const float* __restrict__ bout,
                      float* __restrict__ out) {
    int gid  = (blockIdx.x * blockDim.x + threadIdx.x) >> 5;
    int lane = threadIdx.x & 31;
    if (gid >= N_GRAPHS) return;
    float inv = 1.0f / fmaxf(g_gcnt[gid], 1.0f);
    float p0 = 0.f, p1 = 0.f;
    #pragma unroll
    for (int t = 0; t < 2; t++) {
        int j = lane * 2 + t;
        float v = g_pool[(size_t)gid * DIM + j] * inv;
        p0 += v * __ldg(Wout + j * 2 + 0);
        p1 += v * __ldg(Wout + j * 2 + 1);
    }
    #pragma unroll
    for (int off = 16; off; off >>= 1) {
        p0 += __shfl_down_sync(0xFFFFFFFFu, p0, off);
        p1 += __shfl_down_sync(0xFFFFFFFFu, p1, off);
    }
    if (lane == 0) {
        out[gid * 2 + 0] = p0 + __ldg(bout + 0);
        out[gid * 2 + 1] = p1 + __ldg(bout + 1);
    }
}

// ---------------- launch ---------------------------------------------------
extern "C" void kernel_launch(void* const* d_in, const int* in_sizes, int n_in,
                              void* d_out, int out_size) {
    const int*   x     = (const int*)  d_in[0];
    const int*   ei    = (const int*)  d_in[1];   // [2, E] row-major
    const int*   batch = (const int*)  d_in[2];
    const float* emb   = (const float*)d_in[3];
    const float* W1l   = (const float*)d_in[4];
    const float* b1    = (const float*)d_in[5];
    const float* W1r   = (const float*)d_in[6];
    const float* W2l   = (const float*)d_in[7];
    const float* b2    = (const float*)d_in[8];
    const float* W2r   = (const float*)d_in[9];
    const float* Wout  = (const float*)d_in[10];
    const float* bout  = (const float*)d_in[11];
    float* out = (float*)d_out;

    const int* src = ei;
    const int* dst = ei + N_EDGES;

    const int ZSTATS = (N_GRAPHS * DIM > N_NODES) ? N_GRAPHS * DIM : N_NODES;
    const int TBLK   = (N_NODES + 127) / 128;
    const int ABLK   = (N_NODES * 32 + 255) / 256;     // warp per node
    const int PTHREADS = (N_NODES / 8) * 16;

    // ---- CSR build (once; reused by both layers) ----
    k_zero_stats<<<(ZSTATS + 255) / 256, 256>>>();
    k_hist <<<(N_EDGES + 255) / 256, 256>>>(dst, batch);
    k_scan1<<<N_CHUNKS, SCAN_BS>>>();
    k_scan2<<<1, 128>>>();
    k_scan3<<<N_CHUNKS, SCAN_BS>>>();
    k_fill <<<(N_EDGES + 255) / 256, 256>>>(src, dst);

    // layer 1
    k_transform<1><<<TBLK, 128>>>(emb, x, W1l, W1r, b1);
    k_agg         <<<ABLK, 256>>>();

    // layer 2 (layer-1 node epilogue fused into transform staging)
    k_transform<2><<<TBLK, 128>>>(nullptr, nullptr, W2l, W2r, b2);
    k_agg         <<<ABLK, 256>>>();

    // pool (layer-2 node epilogue fused) + classifier
    k_pool<<<(PTHREADS + 255) / 256, 256>>>(batch);
    k_out <<<(N_GRAPHS * 32 + 255) / 256, 256>>>(Wout, bout, out);
}

// round 14
// speedup vs baseline: 1.7191x; 1.0007x over previous
#include <cuda_runtime.h>
#include <cstddef>

#define N_NODES  100000
#define N_EDGES  1000000
#define DIM      64
#define N_GRAPHS 2048
#define SCAN_BS  1024
#define N_CHUNKS ((N_NODES + SCAN_BS - 1) / SCAN_BS)   // 98

// ---------------- scratch (device globals; no allocation allowed) ----------
__device__ float g_t   [N_NODES * DIM];   // h @ W_l  (message term)
__device__ float g_r   [N_NODES * DIM];   // h @ W_r + b (self term)
__device__ float g_agg [N_NODES * DIM];   // per-node mean of neighbor messages
__device__ float g_pool[N_GRAPHS * DIM];  // graph sums
__device__ float g_gcnt[N_GRAPHS];        // graph node counts
__device__ int   g_cnt [N_NODES];         // in-degree (CSR row lengths)
__device__ int   g_beg [N_NODES];         // CSR row starts (exclusive scan)
__device__ int   g_cur [N_NODES];         // fill cursors
__device__ int   g_esrc[N_EDGES];         // CSR: src node per slot
__device__ int   g_csum[128];             // per-chunk sums

// sm_90+ vectorized global reduction (4 floats per op)
__device__ __forceinline__ void red4(float* p, float4 v) {
    asm volatile("red.global.add.v4.f32 [%0], {%1,%2,%3,%4};"
                 :: "l"(p), "f"(v.x), "f"(v.y), "f"(v.z), "f"(v.w) : "memory");
}

// packed fp32x2 helpers (sm_100+; full-rate fp32 path, bit-exact vs scalar FFMA)
__device__ __forceinline__ void ffma2(unsigned long long& acc,
                                      unsigned long long w,
                                      unsigned long long h) {
    asm("fma.rn.f32x2 %0, %1, %2, %0;" : "+l"(acc) : "l"(w), "l"(h));
}
__device__ __forceinline__ void fadd2(unsigned long long& acc, unsigned long long b) {
    asm("add.rn.f32x2 %0, %1, %0;" : "+l"(acc) : "l"(b));
}
__device__ __forceinline__ unsigned long long fpack2(float v) {
    unsigned long long r;
    asm("mov.b64 %0, {%1, %1};" : "=l"(r) : "f"(v));
    return r;
}

// ---------------- init ------------------------------------------------------
__global__ void k_zero_stats() {
    int i = blockIdx.x * blockDim.x + threadIdx.x;
    if (i < N_NODES)        g_cnt[i]  = 0;
    if (i < N_GRAPHS * DIM) g_pool[i] = 0.f;
    if (i < N_GRAPHS)       g_gcnt[i] = 0.f;
}

// ---------------- histogram: in-degree + graph counts ----------------------
__global__ void k_hist(const int* __restrict__ dst, const int* __restrict__ batch) {
    int i = blockIdx.x * blockDim.x + threadIdx.x;
    if (i < N_EDGES) atomicAdd(&g_cnt[dst[i]], 1);
    if (i < N_NODES) atomicAdd(&g_gcnt[batch[i]], 1.0f);
}

// ---------------- scan pass 1: per-chunk sums ------------------------------
__global__ __launch_bounds__(SCAN_BS) void k_scan1() {
    __shared__ int sh[SCAN_BS / 32];
    int t = threadIdx.x, lane = t & 31, wid = t >> 5;
    int i = blockIdx.x * SCAN_BS + t;
    int v = (i < N_NODES) ? g_cnt[i] : 0;
    #pragma unroll
    for (int off = 16; off; off >>= 1)
        v += __shfl_down_sync(0xFFFFFFFFu, v, off);
    if (lane == 0) sh[wid] = v;
    __syncthreads();
    if (wid == 0) {
        int s = sh[lane];
        #pragma unroll
        for (int off = 16; off; off >>= 1)
            s += __shfl_down_sync(0xFFFFFFFFu, s, off);
        if (lane == 0) g_csum[blockIdx.x] = s;
    }
}

// ---------------- scan pass 2 (fused): local scan + own chunk offset -------
__global__ __launch_bounds__(SCAN_BS) void k_scan3() {
    __shared__ int wsum[SCAN_BS / 32];
    __shared__ int chunk_off;
    int t = threadIdx.x, lane = t & 31, wid = t >> 5;
    int i = blockIdx.x * SCAN_BS + t;
    int v = (i < N_NODES) ? g_cnt[i] : 0;

    // warp-level inclusive scan
    int incl = v;
    #pragma unroll
    for (int off = 1; off < 32; off <<= 1) {
        int u = __shfl_up_sync(0xFFFFFFFFu, incl, off);
        if (lane >= off) incl += u;
    }
    if (lane == 31) wsum[wid] = incl;
    __syncthreads();

    if (wid == 0) {            // exclusive scan of the 32 warp sums
        int s = wsum[lane];
        int sc = s;
        #pragma unroll
        for (int off = 1; off < 32; off <<= 1) {
            int u = __shfl_up_sync(0xFFFFFFFFu, sc, off);
            if (lane >= off) sc += u;
        }
        wsum[lane] = sc - s;
    } else if (wid == 1) {     // this block's chunk offset: sum csum[c<bid]
        int s = 0;
        for (int c = lane; c < N_CHUNKS; c += 32)
            if (c < blockIdx.x) s += g_csum[c];
        #pragma unroll
        for (int off = 16; off; off >>= 1)
            s += __shfl_down_sync(0xFFFFFFFFu, s, off);
        if (lane == 0) chunk_off = s;
    }
    __syncthreads();

    if (i < N_NODES) {
        int excl = chunk_off + wsum[wid] + incl - v;
        g_beg[i] = excl;
        g_cur[i] = excl;
    }
}

// ---------------- CSR fill ---------------------------------------------------
__global__ void k_fill(const int* __restrict__ src, const int* __restrict__ dst) {
    int e = blockIdx.x * blockDim.x + threadIdx.x;
    if (e >= N_EDGES) return;
    int slot = atomicAdd(&g_cur[dst[e]], 1);
    g_esrc[slot] = src[e];
}

// ---------------- fused dual matmul:  t = h@Wl ;  r = h@Wr + b -------------
// One thread per node. h-row in 64 regs; Wl|Wr in a 64x128 smem tile read as
// warp-broadcast 16B loads. Inner math in packed fp32x2 (FFMA2): jt-tiles of
// 8 f4-columns, k innermost, {h,h} packed once per k per tile.
// LAYER==1: h = emb[x[i]].  LAYER==2: h = relu(agg + r) (agg already mean).
template<int LAYER>
__global__ __launch_bounds__(128, 4) void k_transform(
    const float* __restrict__ emb, const int* __restrict__ xidx,
    const float* __restrict__ Wl, const float* __restrict__ Wr,
    const float* __restrict__ b)
{
    __shared__ ulonglong2 Ws2[DIM * 32];        // [k][c4]; c4<16 -> Wl, else Wr
    __shared__ __align__(16) float bs[DIM];
    float* Wsf = reinterpret_cast<float*>(Ws2);

    int tid = threadIdx.x;
    for (int idx = tid; idx < DIM * DIM; idx += 128) {
        int row = idx >> 6, col = idx & 63;
        Wsf[row * 128 + col]      = Wl[idx];
        Wsf[row * 128 + 64 + col] = Wr[idx];
    }
    if (tid < DIM) bs[tid] = b[tid];
    __syncthreads();

    int i = blockIdx.x * 128 + tid;
    if (i >= N_NODES) return;

    float hv[DIM];
    if (LAYER == 1) {
        const float* hrow = emb + (size_t)__ldg(xidx + i) * DIM;
        #pragma unroll
        for (int k = 0; k < DIM / 4; k++) {
            float4 v = __ldg(reinterpret_cast<const float4*>(hrow) + k);
            hv[4 * k + 0] = v.x; hv[4 * k + 1] = v.y;
            hv[4 * k + 2] = v.z; hv[4 * k + 3] = v.w;
        }
    } else {
        const float4* ap = reinterpret_cast<const float4*>(g_agg) + (size_t)i * 16;
        const float4* rp = reinterpret_cast<const float4*>(g_r)   + (size_t)i * 16;
        #pragma unroll
        for (int k = 0; k < DIM / 4; k++) {
            float4 a = __ldg(ap + k);
            float4 r = __ldg(rp + k);
            hv[4 * k + 0] = fmaxf(a.x + r.x, 0.f);
            hv[4 * k + 1] = fmaxf(a.y + r.y, 0.f);
            hv[4 * k + 2] = fmaxf(a.z + r.z, 0.f);
            hv[4 * k + 3] = fmaxf(a.w + r.w, 0.f);
        }
    }

    ulonglong2* tout = reinterpret_cast<ulonglong2*>(g_t) + (size_t)i * 16;
    ulonglong2* rout = reinterpret_cast<ulonglong2*>(g_r) + (size_t)i * 16;
    const ulonglong2* bs2 = reinterpret_cast<const ulonglong2*>(bs);

    for (int g = 0; g < 4; g++) {               // 4 tiles of 8 f4-columns
        unsigned long long acc[16];
        #pragma unroll
        for (int j = 0; j < 16; j++) acc[j] = 0ull;   // bits of {0.f,0.f}

        const ulonglong2* wp = Ws2 + g * 8;
        #pragma unroll
        for (int k = 0; k < DIM; k++) {
            unsigned long long h2 = fpack2(hv[k]);    // one pack per k per tile
            #pragma unroll
            for (int j = 0; j < 8; j++) {
                ulonglong2 w = wp[k * 32 + j];        // warp-broadcast LDS.128
                ffma2(acc[2 * j],     w.x, h2);
                ffma2(acc[2 * j + 1], w.y, h2);
            }
        }

        if (g < 2) {
            #pragma unroll
            for (int j = 0; j < 8; j++)
                tout[g * 8 + j] = make_ulonglong2(acc[2 * j], acc[2 * j + 1]);
        } else {
            #pragma unroll
            for (int j = 0; j < 8; j++) {
                int c = (g - 2) * 8 + j;
                ulonglong2 bb = bs2[c];
                fadd2(acc[2 * j],     bb.x);
                fadd2(acc[2 * j + 1], bb.y);
                rout[c] = make_ulonglong2(acc[2 * j], acc[2 * j + 1]);
            }
        }
    }
}

// ---------------- CSR gather-aggregate:  agg[i] = mean_{s in N(i)} t[s] ----
// One warp per destination node; coalesced full-row loads; atomic-free.
__global__ __launch_bounds__(256) void k_agg() {
    int w    = (blockIdx.x * blockDim.x + threadIdx.x) >> 5;
    int lane = threadIdx.x & 31;
    if (w >= N_NODES) return;
    int beg = __ldg(&g_beg[w]);
    int cnt = __ldg(&g_cnt[w]);

    const float2* tb = reinterpret_cast<const float2*>(g_t);
    float2 a0 = make_float2(0.f, 0.f), a1 = make_float2(0.f, 0.f);

    for (int j0 = 0; j0 < cnt; j0 += 32) {
        int jj = j0 + lane;
        int s_pre = (jj < cnt) ? __ldg(g_esrc + beg + jj) : 0;
        int m = min(cnt - j0, 32);
        int u = 0;
        for (; u + 1 < m; u += 2) {
            int s0 = __shfl_sync(0xFFFFFFFFu, s_pre, u);
            int s1 = __shfl_sync(0xFFFFFFFFu, s_pre, u + 1);
            float2 v0 = __ldg(tb + (size_t)s0 * 32 + lane);
            float2 v1 = __ldg(tb + (size_t)s1 * 32 + lane);
            a0.x += v0.x; a0.y += v0.y;
            a1.x += v1.x; a1.y += v1.y;
        }
        if (u < m) {
            int s0 = __shfl_sync(0xFFFFFFFFu, s_pre, u);
            float2 v0 = __ldg(tb + (size_t)s0 * 32 + lane);
            a0.x += v0.x; a0.y += v0.y;
        }
    }
    float sc = 1.0f / fmaxf((float)cnt, 1.0f);
    float2 out;
    out.x = (a0.x + a1.x) * sc;
    out.y = (a0.y + a1.y) * sc;
    reinterpret_cast<float2*>(g_agg)[(size_t)w * 32 + lane] = out;
}

// ---------------- pool: fused node epilogue + sorted-run aggregation -------
__global__ void k_pool(const int* __restrict__ batch) {
    int gid = blockIdx.x * blockDim.x + threadIdx.x;
    int c4 = gid & 15;
    int n0 = (gid >> 4) * 8;
    if (n0 >= N_NODES) return;

    float4 accum = make_float4(0.f, 0.f, 0.f, 0.f);
    int cur_g = __ldg(batch + n0);
    #pragma unroll
    for (int j = 0; j < 8; j++) {
        int node = n0 + j;                       // N_NODES % 8 == 0: no guard
        int g = __ldg(batch + node);
        if (g != cur_g) {
            red4(&g_pool[(size_t)cur_g * DIM + c4 * 4], accum);
            accum = make_float4(0.f, 0.f, 0.f, 0.f);
            cur_g = g;
        }
        float4 a = reinterpret_cast<const float4*>(g_agg)[(size_t)node * 16 + c4];
        float4 r = reinterpret_cast<const float4*>(g_r  )[(size_t)node * 16 + c4];
        accum.x += fmaxf(a.x + r.x, 0.f);
        accum.y += fmaxf(a.y + r.y, 0.f);
        accum.z += fmaxf(a.z + r.z, 0.f);
        accum.w += fmaxf(a.w + r.w, 0.f);
    }
    red4(&g_pool[(size_t)cur_g * DIM + c4 * 4], accum);
}

// ---------------- classifier:  out = (pool/gcnt) @ Wout + bout -------------
__global__ void k_out(const float* __restrict__ Wout, const float* __restrict__ bout,
                      float* __restrict__ out) {
    int gid  = (blockIdx.x * blockDim.x + threadIdx.x) >> 5;
    int lane = threadIdx.x & 31;
    if (gid >= N_GRAPHS) return;
    float inv = 1.0f / fmaxf(g_gcnt[gid], 1.0f);
    float p0 = 0.f, p1 = 0.f;
    #pragma unroll
    for (int t = 0; t < 2; t++) {
        int j = lane * 2 + t;
        float v = g_pool[(size_t)gid * DIM + j] * inv;
        p0 += v * __ldg(Wout + j * 2 + 0);
        p1 += v * __ldg(Wout + j * 2 + 1);
    }
    #pragma unroll
    for (int off = 16; off; off >>= 1) {
        p0 += __shfl_down_sync(0xFFFFFFFFu, p0, off);
        p1 += __shfl_down_sync(0xFFFFFFFFu, p1, off);
    }
    if (lane == 0) {
        out[gid * 2 + 0] = p0 + __ldg(bout + 0);
        out[gid * 2 + 1] = p1 + __ldg(bout + 1);
    }
}

// ---------------- launch ---------------------------------------------------
extern "C" void kernel_launch(void* const* d_in, const int* in_sizes, int n_in,
                              void* d_out, int out_size) {
    const int*   x     = (const int*)  d_in[0];
    const int*   ei    = (const int*)  d_in[1];   // [2, E] row-major
    const int*   batch = (const int*)  d_in[2];
    const float* emb   = (const float*)d_in[3];
    const float* W1l   = (const float*)d_in[4];
    const float* b1    = (const float*)d_in[5];
    const float* W1r   = (const float*)d_in[6];
    const float* W2l   = (const float*)d_in[7];
    const float* b2    = (const float*)d_in[8];
    const float* W2r   = (const float*)d_in[9];
    const float* Wout  = (const float*)d_in[10];
    const float* bout  = (const float*)d_in[11];
    float* out = (float*)d_out;

    const int* src = ei;
    const int* dst = ei + N_EDGES;

    const int ZSTATS = (N_GRAPHS * DIM > N_NODES) ? N_GRAPHS * DIM : N_NODES;
    const int TBLK   = (N_NODES + 127) / 128;
    const int ABLK   = (N_NODES * 32 + 255) / 256;     // warp per node
    const int PTHREADS = (N_NODES / 8) * 16;

    // ---- CSR build (once; reused by both layers) ----
    k_zero_stats<<<(ZSTATS + 255) / 256, 256>>>();
    k_hist <<<(N_EDGES + 255) / 256, 256>>>(dst, batch);
    k_scan1<<<N_CHUNKS, SCAN_BS>>>();
    k_scan3<<<N_CHUNKS, SCAN_BS>>>();
    k_fill <<<(N_EDGES + 255) / 256, 256>>>(src, dst);

    // layer 1
    k_transform<1><<<TBLK, 128>>>(emb, x, W1l, W1r, b1);
    k_agg         <<<ABLK, 256>>>();

    // layer 2 (layer-1 node epilogue fused into transform staging)
    k_transform<2><<<TBLK, 128>>>(nullptr, nullptr, W2l, W2r, b2);
    k_agg         <<<ABLK, 256>>>();

    // pool (layer-2 node epilogue fused) + classifier
    k_pool<<<(PTHREADS + 255) / 256, 256>>>(batch);
    k_out <<<(N_GRAPHS * 32 + 255) / 256, 256>>>(Wout, bout, out);
}